// round 15
// baseline (speedup 1.0000x reference)
#include <cuda_runtime.h>
#include <cuda_bf16.h>
#include <math.h>

#define BS 32
#define NQ 900
#define NC 91
#define NT 30
#define NTT (BS * NT)   // 960
#define NTH 512          // threads per block (16 warps)

// slice: g_slice[b][t][q] = C[b, q, b*NT + t]
__device__ float g_slice[BS * NT * NQ];
__device__ int   g_done[BS];

// ---------------------------------------------------------------------------
struct CostSm {
    float4 xy[NTT];            // bx0,by0,bx1,by1
    float4 cw[NTT];            // tx,ty,tw,th
    float  areaB[NTT];
    int    lab[NTT];
    float  sprob[32][NC + 1];  // (5 - prob)
};
struct LsaSm {
    double u[NT + 2];
    double keyc[NT + 2];
    unsigned long long rp[2][16];
    int    chosen[NT + 2];
    int    p[NQ + 1];
    unsigned short way[NQ];
    int    jm[NT];
    int    freeRows[NT];
    int    nFree;
};
union SmemU { CostSm c; LsaSm l; };

// cost = 5*l1 + (5-p) - 2*(inter*encl + uni^2)/(uni*encl)
// with encl_w = (w+tw) - dx, dx = min(ax1,bx1) - max(ax0,bx0) (pre-clamp)
__device__ __forceinline__ float pair_cost(
    float cx, float cy, float w, float h,
    float ax0, float ay0, float ax1, float ay1, float areaA, float ccp4,
    float tx, float ty, float tw, float th,
    float bx0, float by0, float bx1, float by1, float areaB)
{
    const float l1 = (fabsf(cx - tx) + fabsf(cy - ty))
                   + (fabsf(w - tw) + fabsf(h - th));
    const float dx = fminf(ax1, bx1) - fmaxf(ax0, bx0);
    const float dy = fminf(ay1, by1) - fmaxf(ay0, by0);
    const float iw = fmaxf(dx, 0.0f);
    const float ih = fmaxf(dy, 0.0f);
    const float inter = iw * ih;
    const float ew = (w + tw) - dx;
    const float eh = (h + th) - dy;
    const float encl = ew * eh;
    const float uni = areaA + areaB - inter;
    const float num = fmaf(inter, encl, uni * uni);
    const float q = __fdividef(num, uni * encl);
    return fmaf(5.0f, l1, ccp4) - 2.0f * q;
}

__device__ __forceinline__ unsigned long long dmap(double d) {
    long long s = __double_as_longlong(d);
    return (unsigned long long)(s < 0 ? ~s : (s | 0x8000000000000000ll));
}
__device__ __forceinline__ double dunmap(unsigned long long u) {
    long long s = (u & 0x8000000000000000ull)
                ? (long long)(u & 0x7fffffffffffffffull)
                : ~(long long)u;
    return __longlong_as_double(s);
}
// pack candidate + column: key truncated at 16 low bits, idx in low 16
__device__ __forceinline__ unsigned long long packkey(double d, int j) {
    return (dmap(d) & ~0xFFFFull) | (unsigned long long)j;
}
__device__ __forceinline__ double unpackval(unsigned long long pk) {
    return dunmap(pk & ~0xFFFFull);
}

// ---------------------------------------------------------------------------
// Slice role: compute g_slice for one batch fast, then raise g_done[b].
// ---------------------------------------------------------------------------
__device__ void slice_role(int b,
    const float* __restrict__ logits, const float* __restrict__ boxes,
    const int* __restrict__ labels, const float* __restrict__ tboxes)
{
    const int tid = threadIdx.x, warp = tid >> 5, lane = tid & 31;

    int lab_t = 0;
    float tx = 0, ty = 0, tw = 0, th = 0, bx0 = 0, by0 = 0, bx1 = 0, by1 = 0, areaB = 0;
    if (lane < NT) {
        lab_t = labels[b * NT + lane];
        const float4 tb = reinterpret_cast<const float4*>(tboxes)[b * NT + lane];
        tx = tb.x; ty = tb.y; tw = tb.z; th = tb.w;
        bx0 = tx - 0.5f * tw; by0 = ty - 0.5f * th;
        bx1 = tx + 0.5f * tw; by1 = ty + 0.5f * th;
        areaB = (bx1 - bx0) * (by1 - by0);
    }

    for (int q = warp; q < NQ; q += 16) {
        const float* lr = logits + ((size_t)b * NQ + q) * NC;
        const float a0 = lr[lane];
        const float a1 = lr[lane + 32];
        const float a2 = (lane < NC - 64) ? lr[lane + 64] : -1e30f;
        float m = fmaxf(fmaxf(a0, a1), a2);
        #pragma unroll
        for (int o = 16; o; o >>= 1) m = fmaxf(m, __shfl_xor_sync(~0u, m, o));
        float s = __expf(a0 - m) + __expf(a1 - m)
                + ((lane < NC - 64) ? __expf(a2 - m) : 0.0f);
        #pragma unroll
        for (int o = 16; o; o >>= 1) s += __shfl_xor_sync(~0u, s, o);
        if (lane < NT) {
            const float ccp4 = 5.0f - __fdividef(__expf(__ldg(&lr[lab_t]) - m), s);
            const float4 pb = reinterpret_cast<const float4*>(boxes)[b * NQ + q];
            const float ax0 = pb.x - 0.5f * pb.z, ay0 = pb.y - 0.5f * pb.w;
            const float ax1 = pb.x + 0.5f * pb.z, ay1 = pb.y + 0.5f * pb.w;
            const float areaA = (ax1 - ax0) * (ay1 - ay0);
            g_slice[((size_t)(b * NT + lane)) * NQ + q] =
                pair_cost(pb.x, pb.y, pb.z, pb.w, ax0, ay0, ax1, ay1, areaA, ccp4,
                          tx, ty, tw, th, bx0, by0, bx1, by1, areaB);
        }
    }
    __syncthreads();
    __threadfence();
    if (tid == 0) atomicExch(&g_done[b], 1);
}

// ---------------------------------------------------------------------------
// LSA role: JV, greedy dual init, deferred duals, packed u64 argmin.
// Cost rows read from L2 (g_slice); smem footprint is small.
// ---------------------------------------------------------------------------
__device__ void lsa_role(SmemU& sm, int b, float* outPred, float* outTgt)
{
    const int tid = threadIdx.x, warp = tid >> 5, lane = tid & 31;

    if (tid == 0) { while (atomicAdd(&g_done[b], 0) == 0) __nanosleep(128); }
    __syncthreads();
    __threadfence();

    const unsigned long long KINF = 0xffffffffffffffffull;
    const bool act = (tid * 2 < NQ);   // tid < 450
    const float* __restrict__ cost = g_slice + (size_t)b * NT * NQ;

    for (int j = tid; j < NQ; j += NTH) sm.l.p[j + 1] = 0;
    double v[2] = {0.0, 0.0};
    int par = 0;
    __syncthreads();

    // ---- greedy dual init: u[i] = row min (truncated key), argmin column ----
    for (int r = warp; r < NT; r += 16) {
        const float* crow = cost + (size_t)r * NQ;
        unsigned long long mk = KINF;
        for (int j = lane; j < NQ; j += 32)
            mk = min(mk, packkey((double)__ldg(&crow[j]), j));
        #pragma unroll
        for (int o = 16; o; o >>= 1)
            mk = min(mk, __shfl_down_sync(~0u, mk, o));
        if (lane == 0) {
            sm.l.u[r + 1] = unpackval(mk);
            sm.l.jm[r] = (int)(mk & 0xFFFF);
        }
    }
    __syncthreads();
    if (tid == 0) {
        int nf = 0;
        for (int i = 1; i <= NT; i++) {
            const int j = sm.l.jm[i - 1];
            if (sm.l.p[j + 1] == 0) sm.l.p[j + 1] = i;
            else sm.l.freeRows[nf++] = i;
        }
        sm.l.nFree = nf;
    }
    __syncthreads();
    const int nFree = sm.l.nFree;

    // ---- augmenting phases for unassigned rows only ----
    for (int fi = 0; fi < nFree; fi++) {
        const int i = sm.l.freeRows[fi];
        unsigned long long key[2] = {KINF, KINF};
        int usedm = 0;
        int i0 = i, j0 = 0, S = 0;
        double Dprev = 0.0;

        while (true) {
            const double K = Dprev - sm.l.u[i0];
            const float* __restrict__ crow = cost + (size_t)(i0 - 1) * NQ;

            unsigned long long bk = KINF;
            if (act) {
                const float2 c2 = __ldg(reinterpret_cast<const float2*>(crow + 2 * tid));
                const float cv[2] = {c2.x, c2.y};
                #pragma unroll
                for (int k = 0; k < 2; k++) {
                    if (!((usedm >> k) & 1)) {
                        const double cand = ((double)cv[k] - v[k]) + K;
                        const unsigned long long pk = packkey(cand, 2 * tid + k);
                        if (pk < key[k]) {
                            key[k] = pk;
                            sm.l.way[2 * tid + k] = (unsigned short)j0;
                        }
                        bk = min(bk, key[k]);
                    }
                }
            }
            #pragma unroll
            for (int o = 16; o; o >>= 1)
                bk = min(bk, __shfl_down_sync(~0u, bk, o));
            if (lane == 0) sm.l.rp[par][warp] = bk;
            __syncthreads();                       // the ONLY barrier per step

            unsigned long long mk = (lane < 16) ? sm.l.rp[par][lane] : KINF;
            #pragma unroll
            for (int o = 8; o; o >>= 1)
                mk = min(mk, __shfl_down_sync(~0u, mk, o));
            mk = __shfl_sync(~0u, mk, 0);

            const int j1 = (int)(mk & 0xFFFF);
            Dprev = unpackval(mk);
            if (tid == 0) { sm.l.chosen[S] = j1; sm.l.keyc[S] = Dprev; }
            const int ni0 = sm.l.p[j1 + 1];        // broadcast smem read
            if (act && (j1 >> 1) == tid) usedm |= 1 << (j1 & 1);
            j0 = j1 + 1;
            S++;
            par ^= 1;
            if (ni0 == 0) break;
            i0 = ni0;
        }
        __syncthreads();   // chosen/keyc/way visible; scans finished

        // phase-end dual updates (before augment)
        if (tid == 0) {
            sm.l.u[i] += Dprev;
        } else if (tid < S) {
            const int c = sm.l.chosen[tid - 1];
            sm.l.u[sm.l.p[c + 1]] += Dprev - sm.l.keyc[tid - 1];
        }
        if (act) {
            for (int s = 0; s < S - 1; s++) {
                const int c = sm.l.chosen[s];
                if ((c >> 1) == tid) v[c & 1] -= Dprev - sm.l.keyc[s];
            }
        }
        __syncthreads();

        // augment: predecessor 0 is the virtual root column holding row i
        if (tid == 0) {
            int jj = sm.l.chosen[S - 1] + 1;
            while (jj) {
                const int jn = (int)sm.l.way[jj - 1];
                sm.l.p[jj] = jn ? sm.l.p[jn] : i;
                jj = jn;
            }
        }
        __syncthreads();
    }

    if (tid == 0) {
        int preds[NT];
        for (int j = 1; j <= NQ; j++)
            if (sm.l.p[j] > 0) preds[sm.l.p[j] - 1] = j - 1;
        int order[NT];
        for (int k = 0; k < NT; k++) order[k] = k;
        for (int a = 1; a < NT; a++) {
            const int o = order[a];
            const int kv = preds[o];
            int c = a - 1;
            while (c >= 0 && preds[order[c]] > kv) { order[c + 1] = order[c]; c--; }
            order[c + 1] = o;
        }
        for (int k = 0; k < NT; k++) {
            outPred[b * NT + k] = (float)preds[order[k]];
            outTgt[b * NT + k]  = (float)order[k];
        }
    }
}

// ---------------------------------------------------------------------------
// Cost role: 32 rows per block (2 rows/warp), streams all 960 columns.
// ---------------------------------------------------------------------------
__device__ void cost_role(SmemU& sm, int cb,
    const float* __restrict__ logits, const float* __restrict__ boxes,
    const int* __restrict__ labels, const float* __restrict__ tboxes,
    float* __restrict__ C)
{
    const int tid = threadIdx.x, warp = tid >> 5, lane = tid & 31;

    for (int j = tid; j < NTT; j += NTH) {
        const float4 tb = reinterpret_cast<const float4*>(tboxes)[j];
        const float bx0 = tb.x - 0.5f * tb.z, by0 = tb.y - 0.5f * tb.w;
        const float bx1 = tb.x + 0.5f * tb.z, by1 = tb.y + 0.5f * tb.w;
        sm.c.cw[j] = tb;
        sm.c.xy[j] = make_float4(bx0, by0, bx1, by1);
        sm.c.areaB[j] = (bx1 - bx0) * (by1 - by0);
        sm.c.lab[j] = labels[j];
    }
    __syncthreads();

    const int rbase = cb * 32 + warp * 2;   // cost grid = 900 exactly

    #pragma unroll
    for (int rr = 0; rr < 2; rr++) {
        const int row = rbase + rr;
        const float* lr = logits + (size_t)row * NC;
        const float a0 = lr[lane];
        const float a1 = lr[lane + 32];
        const float a2 = (lane < NC - 64) ? lr[lane + 64] : -1e30f;
        float m = fmaxf(fmaxf(a0, a1), a2);
        #pragma unroll
        for (int o = 16; o; o >>= 1) m = fmaxf(m, __shfl_xor_sync(~0u, m, o));
        const float e0 = __expf(a0 - m);
        const float e1 = __expf(a1 - m);
        const float e2 = (lane < NC - 64) ? __expf(a2 - m) : 0.0f;
        float s = e0 + e1 + e2;
        #pragma unroll
        for (int o = 16; o; o >>= 1) s += __shfl_xor_sync(~0u, s, o);
        const float inv = __fdividef(1.0f, s);
        sm.c.sprob[warp * 2 + rr][lane]      = fmaf(e0, -inv, 5.0f);
        sm.c.sprob[warp * 2 + rr][lane + 32] = fmaf(e1, -inv, 5.0f);
        if (lane < NC - 64) sm.c.sprob[warp * 2 + rr][lane + 64] = fmaf(e2, -inv, 5.0f);
    }
    __syncwarp();

    const float4 p0 = reinterpret_cast<const float4*>(boxes)[rbase];
    const float4 p1 = reinterpret_cast<const float4*>(boxes)[rbase + 1];
    const float ax00 = p0.x - 0.5f * p0.z, ay00 = p0.y - 0.5f * p0.w;
    const float ax01 = p0.x + 0.5f * p0.z, ay01 = p0.y + 0.5f * p0.w;
    const float arA0 = (ax01 - ax00) * (ay01 - ay00);
    const float ax10 = p1.x - 0.5f * p1.z, ay10 = p1.y - 0.5f * p1.w;
    const float ax11 = p1.x + 0.5f * p1.z, ay11 = p1.y + 0.5f * p1.w;
    const float arA1 = (ax11 - ax10) * (ay11 - ay10);

    const float* pr0 = sm.c.sprob[warp * 2];
    const float* pr1 = sm.c.sprob[warp * 2 + 1];
    float* __restrict__ c0 = C + (size_t)rbase * NTT;
    float* __restrict__ c1 = c0 + NTT;

    #pragma unroll 5
    for (int k = 0; k < 30; k++) {
        const int j = lane + 32 * k;
        const float4 X = sm.c.xy[j];
        const float4 W = sm.c.cw[j];
        const float ab = sm.c.areaB[j];
        const int lb = sm.c.lab[j];
        c0[j] = pair_cost(p0.x, p0.y, p0.z, p0.w, ax00, ay00, ax01, ay01, arA0, pr0[lb],
                          W.x, W.y, W.z, W.w, X.x, X.y, X.z, X.w, ab);
        c1[j] = pair_cost(p1.x, p1.y, p1.z, p1.w, ax10, ay10, ax11, ay11, arA1, pr1[lb],
                          W.x, W.y, W.z, W.w, X.x, X.y, X.z, X.w, ab);
    }
}

// ---------------------------------------------------------------------------
__global__ void reset_kernel() {
    if (threadIdx.x < BS) g_done[threadIdx.x] = 0;
}

__global__ __launch_bounds__(NTH, 3) void fused_kernel(
    const float* __restrict__ logits, const float* __restrict__ boxes,
    const int* __restrict__ labels, const float* __restrict__ tboxes,
    float* __restrict__ C, float* __restrict__ outPred, float* __restrict__ outTgt)
{
    extern __shared__ __align__(16) unsigned char dynsm[];
    SmemU& sm = *reinterpret_cast<SmemU*>(dynsm);

    const int bid = blockIdx.x;
    if (bid < BS) {
        slice_role(bid, logits, boxes, labels, tboxes);
    } else if (bid < 2 * BS) {
        lsa_role(sm, bid - BS, outPred, outTgt);
    } else {
        cost_role(sm, bid - 2 * BS, logits, boxes, labels, tboxes, C);
    }
}

// ---------------------------------------------------------------------------
extern "C" void kernel_launch(void* const* d_in, const int* in_sizes, int n_in,
                              void* d_out, int out_size)
{
    const float* logits = (const float*)d_in[0];   // (32,900,91) f32
    const float* boxes  = (const float*)d_in[1];   // (32,900,4)  f32
    const int*   labels = (const int*)d_in[2];     // (32,30)     i32
    const float* tboxes = (const float*)d_in[3];   // (32,30,4)   f32

    float* out = (float*)d_out;
    float* outC    = out;                                  // 32*900*960
    float* outPred = out + (size_t)BS * NQ * NTT;          // 960
    float* outTgt  = outPred + BS * NT;                    // 960

    cudaFuncSetAttribute(fused_kernel,
                         cudaFuncAttributeMaxDynamicSharedMemorySize,
                         (int)sizeof(SmemU));

    reset_kernel<<<1, 32>>>();
    fused_kernel<<<2 * BS + (BS * NQ) / 32, NTH, sizeof(SmemU)>>>(
        logits, boxes, labels, tboxes, outC, outPred, outTgt);
}